// round 13
// baseline (speedup 1.0000x reference)
#include <cuda_runtime.h>
#include <cuda_fp16.h>

#define N_VARS    100000
#define N_CLAUSES 400000
#define NNZ       1200000
#define D         128
#define DC        64           // features per chunk
#define EPSILON   1e-6f

#define CAP_C 32     // slots per clause  (Poisson mean 3)
#define CAP_V 64     // slots per folded variable (Poisson mean 12)

// ---------------- scratch (static device globals; BSS zeroed at load) --------
__device__ unsigned g_varsh[2 * (size_t)N_VARS * 32];   // vars fp16, chunked: [chunk][var][lane]
__device__ unsigned g_Sh[(size_t)N_CLAUSES * 32];       // ONE chunk of clause sums (reused), 51.2 MB
__device__ float    g_Sdeg[N_CLAUSES];
__device__ float    g_inv[N_VARS];                      // 1/max(deg,2), computed in B0
__device__ float    g_ss[2 * N_VARS];                   // per-chunk partial sum of squares
__device__ int      g_cnt_c[N_CLAUSES];                 // self-resetting cursors
__device__ int      g_cnt_v[N_VARS];
__device__ int2     g_ec[(size_t)N_CLAUSES * CAP_C];    // padded CSR by clause: {var, val}
__device__ int2     g_ev[(size_t)N_VARS * CAP_V];       // padded CSR by var:    {clause, val}

// ---------------- init: convert vars to fp16 chunked layout ------------------
__global__ void k_init(const float* __restrict__ vars) {
    int tid    = blockIdx.x * blockDim.x + threadIdx.x;
    int stride = gridDim.x * blockDim.x;
    const int nw = N_VARS * 64;                 // half2 words total
    const float2* v2 = reinterpret_cast<const float2*>(vars);
    for (int i = tid; i < nw; i += stride) {
        int v = i >> 6;
        int t = i & 63;                          // feature pair within row
        int chunk = t >> 5;
        int lane  = t & 31;
        float2 x = v2[i];
        __half2 h = __floats2half2_rn(x.x, x.y);
        g_varsh[((size_t)chunk * N_VARS + v) * 32 + lane] =
            *reinterpret_cast<unsigned*>(&h);
    }
}

// ---------------- fill padded CSR in one pass --------------------------------
__global__ void k_fill(const int* __restrict__ rows, const int* __restrict__ cols,
                       const float* __restrict__ vals) {
    int e = blockIdx.x * blockDim.x + threadIdx.x;
    if (e >= NNZ) return;
    int   r  = __ldg(rows + e);
    int   c  = __ldg(cols + e);
    float vl = __ldg(vals + e);
    int   v  = (c >= N_VARS) ? (c - N_VARS) : c;     // fold literal halves

    int pc = atomicAdd(&g_cnt_c[r], 1);
    if (pc < CAP_C) g_ec[(size_t)r * CAP_C + pc] = make_int2(v, __float_as_int(vl));

    int pv = atomicAdd(&g_cnt_v[v], 1);
    if (pv < CAP_V) g_ev[(size_t)v * CAP_V + pv] = make_int2(r, __float_as_int(vl));
}

// ---------------- pass A: clause sums for one chunk (warp per clause) --------
__global__ void __launch_bounds__(256)
k_passA(int chunk) {
    int w = (blockIdx.x * blockDim.x + threadIdx.x) >> 5;
    if (w >= N_CLAUSES) return;
    int lane = threadIdx.x & 31;

    int n = g_cnt_c[w];                       // broadcast load
    if (chunk == 1 && lane == 0) g_cnt_c[w] = 0;   // reset at LAST use
    n = min(n, CAP_C);
    if (n == 0) return;                       // empty: never read back

    int2 rec = (lane < n) ? __ldg(&g_ec[(size_t)w * CAP_C + lane]) : make_int2(0, 0);

    const unsigned* vtab = g_varsh + (size_t)chunk * N_VARS * 32;
    float2 sum = make_float2(0.f, 0.f);
    float  deg = 0.f;
    #pragma unroll 4
    for (int j = 0; j < n; j++) {
        int   v   = __shfl_sync(0xffffffffu, rec.x, j);
        float val = __int_as_float(__shfl_sync(0xffffffffu, rec.y, j));
        unsigned h = __ldg(&vtab[(size_t)v * 32 + lane]);       // 128B/warp, 1 line
        float2 f = __half22float2(*reinterpret_cast<__half2*>(&h));
        sum.x += f.x * val;  sum.y += f.y * val;
        deg   += val;
    }
    __half2 hs = __floats2half2_rn(sum.x, sum.y);
    g_Sh[(size_t)w * 32 + lane] = *reinterpret_cast<unsigned*>(&hs);
    if (chunk == 0 && lane == 0) g_Sdeg[w] = deg;
}

// ---------------- pass B: back-gather + center, one chunk (warp per var) -----
__global__ void __launch_bounds__(256)
k_passB(int chunk, const float* __restrict__ vars, float* __restrict__ out) {
    int w = (blockIdx.x * blockDim.x + threadIdx.x) >> 5;
    if (w >= N_VARS) return;
    int lane = threadIdx.x & 31;
    size_t off2 = (size_t)w * (D / 2) + chunk * 32 + lane;   // float2 units

    float2 x = reinterpret_cast<const float2*>(vars)[off2];  // prefetch early

    int n = g_cnt_v[w];
    if (chunk == 1 && lane == 0) g_cnt_v[w] = 0;             // reset at LAST use
    n = min(n, CAP_V);
    const int2* erow = g_ev + (size_t)w * CAP_V;

    float2 acc = make_float2(0.f, 0.f);
    float  deg = 0.f;
    for (int base = 0; base < n; base += 32) {
        int m = min(32, n - base);
        int2 rec = (lane < m) ? __ldg(erow + base + lane) : make_int2(0, 0);
        #pragma unroll 4
        for (int j = 0; j < m; j++) {
            int   c   = __shfl_sync(0xffffffffu, rec.x, j);
            float val = __int_as_float(__shfl_sync(0xffffffffu, rec.y, j));
            unsigned h = __ldg(&g_Sh[(size_t)c * 32 + lane]); // L2-resident chunk
            float2 f = __half22float2(*reinterpret_cast<__half2*>(&h));
            acc.x += f.x * val;  acc.y += f.y * val;
            if (chunk == 0) deg += __ldg(&g_Sdeg[c]) * val;
        }
    }

    float inv;
    if (chunk == 0) {
        inv = 1.0f / fmaxf(deg, 2.0f);
        if (lane == 0) g_inv[w] = inv;
    } else {
        inv = __ldg(&g_inv[w]);
    }

    float2 vv = make_float2(x.x - acc.x * inv, x.y - acc.y * inv);
    reinterpret_cast<float2*>(out)[off2] = vv;

    float ss = vv.x * vv.x + vv.y * vv.y;
    #pragma unroll
    for (int o = 16; o; o >>= 1) ss += __shfl_xor_sync(0xffffffffu, ss, o);
    if (lane == 0) g_ss[chunk * N_VARS + w] = ss;
}

// ---------------- final: apply rsqrt scale in place --------------------------
__global__ void k_norm(float* __restrict__ out) {
    int tid    = blockIdx.x * blockDim.x + threadIdx.x;
    int stride = gridDim.x * blockDim.x;
    const int n4 = N_VARS * (D / 4);
    float4* o4 = reinterpret_cast<float4*>(out);
    for (int i = tid; i < n4; i += stride) {
        int row = i >> 5;                       // 32 float4 per row
        float ss = g_ss[row] + g_ss[N_VARS + row];
        float scale = rsqrtf(ss * (1.0f / 128.0f) + EPSILON);
        float4 o = o4[i];
        o4[i] = make_float4(o.x * scale, o.y * scale, o.z * scale, o.w * scale);
    }
}

// ---------------- launcher ---------------------------------------------------
extern "C" void kernel_launch(void* const* d_in, const int* in_sizes, int n_in,
                              void* d_out, int out_size) {
    const float* vars = (const float*)d_in[0];
    const float* vals = (const float*)d_in[1];
    const int*   rows = (const int*)d_in[2];
    const int*   cols = (const int*)d_in[3];
    float* out = (float*)d_out;

    k_init <<<1024, 256>>>(vars);
    k_fill <<<(NNZ + 255) / 256, 256>>>(rows, cols, vals);

    k_passA<<<(N_CLAUSES * 32 + 255) / 256, 256>>>(0);
    k_passB<<<(N_VARS * 32 + 255) / 256, 256>>>(0, vars, out);
    k_passA<<<(N_CLAUSES * 32 + 255) / 256, 256>>>(1);
    k_passB<<<(N_VARS * 32 + 255) / 256, 256>>>(1, vars, out);

    k_norm <<<3200, 256>>>(out);
}

// round 14
// speedup vs baseline: 1.3959x; 1.3959x over previous
#include <cuda_runtime.h>
#include <cuda_fp16.h>

#define N_VARS    100000
#define N_CLAUSES 400000
#define NNZ       1200000
#define D         128
#define EPSILON   1e-6f
#define CAP_C     32      // slots per clause (Poisson mean 3; P(>32) ~ 0)

// ---------------- scratch (static device globals; BSS zeroed at load) --------
__device__ uint2 g_varsh[(size_t)N_VARS * 32];      // vars fp16: [var][lane], 8B = 4 feats
__device__ float g_acc[(size_t)N_VARS * D];         // fp32 accumulator, 51.2 MB (L2-resident)
__device__ float g_vdeg[N_VARS];
__device__ int   g_cnt_c[N_CLAUSES];                // self-resetting cursors
__device__ int2  g_ec[(size_t)N_CLAUSES * CAP_C];   // padded CSR by clause: {var, val}

__device__ __forceinline__ void red_add_v4(float* p, float4 v) {
    asm volatile("red.global.add.v4.f32 [%0], {%1,%2,%3,%4};"
                 :: "l"(p), "f"(v.x), "f"(v.y), "f"(v.z), "f"(v.w)
                 : "memory");
}
__device__ __forceinline__ void red_add_f(float* p, float v) {
    asm volatile("red.global.add.f32 [%0], %1;" :: "l"(p), "f"(v) : "memory");
}

// ---------------- init: zero acc/vdeg + convert vars to fp16 -----------------
__global__ void k_init(const float* __restrict__ vars) {
    int tid    = blockIdx.x * blockDim.x + threadIdx.x;
    int stride = gridDim.x * blockDim.x;
    float4 z = make_float4(0.f, 0.f, 0.f, 0.f);
    const int na = N_VARS * (D / 4);
    float4* a4 = reinterpret_cast<float4*>(g_acc);
    for (int i = tid; i < na; i += stride) a4[i] = z;
    for (int i = tid; i < N_VARS; i += stride) g_vdeg[i] = 0.f;

    const int nh = N_VARS * 32;                     // uint2 words (4 feats each)
    const float4* v4 = reinterpret_cast<const float4*>(vars);
    for (int i = tid; i < nh; i += stride) {
        float4 x = v4[i];
        __half2 h0 = __floats2half2_rn(x.x, x.y);
        __half2 h1 = __floats2half2_rn(x.z, x.w);
        g_varsh[i] = make_uint2(*reinterpret_cast<unsigned*>(&h0),
                                *reinterpret_cast<unsigned*>(&h1));
    }
}

// ---------------- fill padded clause-CSR in one pass -------------------------
__global__ void k_fill(const int* __restrict__ rows, const int* __restrict__ cols,
                       const float* __restrict__ vals) {
    int e = blockIdx.x * blockDim.x + threadIdx.x;
    if (e >= NNZ) return;
    int   r  = __ldg(rows + e);
    int   c  = __ldg(cols + e);
    float vl = __ldg(vals + e);
    int   v  = (c >= N_VARS) ? (c - N_VARS) : c;     // fold literal halves

    int pc = atomicAdd(&g_cnt_c[r], 1);
    if (pc < CAP_C) g_ec[(size_t)r * CAP_C + pc] = make_int2(v, __float_as_int(vl));
}

// ---------------- fused A^T A pass: one warp per clause ----------------------
// Gather the clause's var rows (fp16, fp32 accumulate), then RED-scatter
// sum*val back to each incident variable. Scatters are fire-and-forget.
__global__ void __launch_bounds__(256)
k_fused() {
    int w = (blockIdx.x * blockDim.x + threadIdx.x) >> 5;
    if (w >= N_CLAUSES) return;
    int lane = threadIdx.x & 31;

    int n = g_cnt_c[w];                      // broadcast load (uniform address)
    if (lane == 0) g_cnt_c[w] = 0;           // reset for next graph replay
    n = min(n, CAP_C);
    if (n == 0) return;

    int2 rec = (lane < n) ? __ldg(&g_ec[(size_t)w * CAP_C + lane]) : make_int2(0, 0);

    float4 sum = make_float4(0.f, 0.f, 0.f, 0.f);
    float  deg = 0.f;
    #pragma unroll 4
    for (int j = 0; j < n; j++) {
        int   v   = __shfl_sync(0xffffffffu, rec.x, j);
        float val = __int_as_float(__shfl_sync(0xffffffffu, rec.y, j));
        uint2 h = __ldg(&g_varsh[(size_t)v * 32 + lane]);   // 256B/warp, fp16
        float2 f0 = __half22float2(*reinterpret_cast<__half2*>(&h.x));
        float2 f1 = __half22float2(*reinterpret_cast<__half2*>(&h.y));
        sum.x += f0.x * val;  sum.y += f0.y * val;
        sum.z += f1.x * val;  sum.w += f1.y * val;
        deg   += val;
    }

    #pragma unroll 4
    for (int j = 0; j < n; j++) {
        int   v   = __shfl_sync(0xffffffffu, rec.x, j);
        float val = __int_as_float(__shfl_sync(0xffffffffu, rec.y, j));
        float4 m = make_float4(sum.x * val, sum.y * val, sum.z * val, sum.w * val);
        red_add_v4(g_acc + (size_t)v * D + lane * 4, m);
        if (lane == 0) red_add_f(&g_vdeg[v], deg * val);
    }
}

// ---------------- normalize: one warp per variable ---------------------------
__global__ void k_norm(const float* __restrict__ vars, float* __restrict__ out) {
    int w = (blockIdx.x * blockDim.x + threadIdx.x) >> 5;
    if (w >= N_VARS) return;
    int lane = threadIdx.x & 31;

    float deg = g_vdeg[w];
    float inv = 1.0f / fmaxf(deg, 2.0f);
    size_t off = (size_t)w * D + lane * 4;

    float4 a = *reinterpret_cast<const float4*>(g_acc + off);
    float4 x = *reinterpret_cast<const float4*>(vars + off);
    float4 vv = make_float4(x.x - a.x * inv, x.y - a.y * inv,
                            x.z - a.z * inv, x.w - a.w * inv);
    float ss = vv.x * vv.x + vv.y * vv.y + vv.z * vv.z + vv.w * vv.w;
    #pragma unroll
    for (int o = 16; o; o >>= 1) ss += __shfl_xor_sync(0xffffffffu, ss, o);
    float scale = rsqrtf(ss * (1.0f / 128.0f) + EPSILON);
    *reinterpret_cast<float4*>(out + off) =
        make_float4(vv.x * scale, vv.y * scale, vv.z * scale, vv.w * scale);
}

// ---------------- launcher ---------------------------------------------------
extern "C" void kernel_launch(void* const* d_in, const int* in_sizes, int n_in,
                              void* d_out, int out_size) {
    const float* vars = (const float*)d_in[0];
    const float* vals = (const float*)d_in[1];
    const int*   rows = (const int*)d_in[2];
    const int*   cols = (const int*)d_in[3];
    float* out = (float*)d_out;

    k_init <<<1024, 256>>>(vars);
    k_fill <<<(NNZ + 255) / 256, 256>>>(rows, cols, vals);
    k_fused<<<(N_CLAUSES * 32 + 255) / 256, 256>>>();
    k_norm <<<(N_VARS * 32 + 255) / 256, 256>>>(vars, out);
}

// round 15
// speedup vs baseline: 3.5717x; 2.5586x over previous
#include <cuda_runtime.h>
#include <cuda_fp16.h>

#define N_VARS    100000
#define N_CLAUSES 400000
#define NNZ       1200000
#define D         128
#define EPSILON   1e-6f
#define CAP       32          // per-clause smem edge cache (avg degree ~3)

// ---------------- scratch (static device globals; compact => L2-resident) ----
struct __align__(16) EdgeRec { int next; int col; float val; int pad; };

__device__ uint2   g_varsh[(size_t)N_VARS * 32];  // vars fp16: [var][lane], 25.6 MB
__device__ float   g_acc[(size_t)N_VARS * D];     // fp32 accumulator, 51.2 MB
__device__ float   g_vdeg[N_VARS];
__device__ int     g_head[N_CLAUSES];
__device__ EdgeRec g_rec[NNZ];                    // 19.2 MB

__device__ __forceinline__ void red_add_v4(float* p, float4 v) {
    asm volatile("red.global.add.v4.f32 [%0], {%1,%2,%3,%4};"
                 :: "l"(p), "f"(v.x), "f"(v.y), "f"(v.z), "f"(v.w)
                 : "memory");
}
__device__ __forceinline__ void red_add_f(float* p, float v) {
    asm volatile("red.global.add.f32 [%0], %1;" :: "l"(p), "f"(v) : "memory");
}

// ---------------- init: zero acc/vdeg, head=-1, convert vars to fp16 ---------
__global__ void k_init(const float* __restrict__ vars) {
    int tid    = blockIdx.x * blockDim.x + threadIdx.x;
    int stride = gridDim.x * blockDim.x;
    float4 z = make_float4(0.f, 0.f, 0.f, 0.f);
    const int na = N_VARS * (D / 4);
    float4* a4 = reinterpret_cast<float4*>(g_acc);
    for (int i = tid; i < na; i += stride) a4[i] = z;
    for (int i = tid; i < N_VARS;    i += stride) g_vdeg[i] = 0.f;
    for (int i = tid; i < N_CLAUSES; i += stride) g_head[i] = -1;

    const int nh = N_VARS * 32;                 // uint2 words (4 floats each)
    const float4* v4 = reinterpret_cast<const float4*>(vars);
    for (int i = tid; i < nh; i += stride) {
        float4 x = v4[i];
        __half2 h0 = __floats2half2_rn(x.x, x.y);
        __half2 h1 = __floats2half2_rn(x.z, x.w);
        g_varsh[i] = make_uint2(*reinterpret_cast<unsigned*>(&h0),
                                *reinterpret_cast<unsigned*>(&h1));
    }
}

// ---------------- build per-clause linked lists ------------------------------
__global__ void k_build(const int* __restrict__ rows,
                        const int* __restrict__ cols,
                        const float* __restrict__ vals) {
    int e = blockIdx.x * blockDim.x + threadIdx.x;
    if (e >= NNZ) return;
    int r = __ldg(rows + e);
    int prev = atomicExch(&g_head[r], e);
    int col = __ldg(cols + e);
    float v = __ldg(vals + e);
    int vv = (col >= N_VARS) ? (col - N_VARS) : col;   // fold literal halves
    *reinterpret_cast<int4*>(&g_rec[e]) = make_int4(prev, vv, __float_as_int(v), 0);
}

// ---------------- fused A^T A pass: one warp per clause ----------------------
// Walk the clause's edge list: gather fp16 var rows into fp32 register sum,
// then RED-scatter sum*val back to each incident variable.
__global__ void __launch_bounds__(256)
k_fused() {
    int w = (blockIdx.x * blockDim.x + threadIdx.x) >> 5;
    if (w >= N_CLAUSES) return;
    int lane  = threadIdx.x & 31;
    int wslot = (threadIdx.x >> 5);
    __shared__ uint2 list[8][CAP];   // (v, val) per cached edge

    int e = g_head[w];
    if (e < 0) return;

    float4 sum = make_float4(0.f, 0.f, 0.f, 0.f);
    float  deg = 0.f;
    int cnt = 0;
    int e_rest = -1;

    while (e >= 0) {
        int4 r = *reinterpret_cast<const int4*>(&g_rec[e]);  // uniform addr, bcast
        int   v   = r.y;
        float val = __int_as_float(r.z);

        uint2 h = __ldg(&g_varsh[(size_t)v * 32 + lane]);    // 256 B/warp, fp16
        float2 f0 = __half22float2(*reinterpret_cast<__half2*>(&h.x));
        float2 f1 = __half22float2(*reinterpret_cast<__half2*>(&h.y));
        sum.x += f0.x * val;  sum.y += f0.y * val;
        sum.z += f1.x * val;  sum.w += f1.y * val;
        deg   += val;

        if (cnt < CAP) {
            if (lane == 0) list[wslot][cnt] = make_uint2((unsigned)v, (unsigned)r.z);
            cnt++;
        } else if (e_rest < 0) {
            e_rest = e;   // overflow tail (practically never)
        }
        e = r.x;
    }
    __syncwarp();

    for (int i = 0; i < cnt; i++) {
        uint2 u = list[wslot][i];
        int   v   = (int)u.x;
        float val = __uint_as_float(u.y);
        float4 m = make_float4(sum.x * val, sum.y * val, sum.z * val, sum.w * val);
        red_add_v4(g_acc + (size_t)v * D + lane * 4, m);
        if (lane == 0) red_add_f(&g_vdeg[v], deg * val);
    }

    while (e_rest >= 0) {   // overflow tail for clauses with >CAP edges
        int4 r = *reinterpret_cast<const int4*>(&g_rec[e_rest]);
        int   v   = r.y;
        float val = __int_as_float(r.z);
        float4 m = make_float4(sum.x * val, sum.y * val, sum.z * val, sum.w * val);
        red_add_v4(g_acc + (size_t)v * D + lane * 4, m);
        if (lane == 0) red_add_f(&g_vdeg[v], deg * val);
        e_rest = r.x;
    }
}

// ---------------- normalize: one warp per variable ---------------------------
__global__ void k_norm(const float* __restrict__ vars, float* __restrict__ out) {
    int w = (blockIdx.x * blockDim.x + threadIdx.x) >> 5;
    if (w >= N_VARS) return;
    int lane = threadIdx.x & 31;

    float deg = g_vdeg[w];
    float inv = 1.0f / fmaxf(deg, 2.0f);
    size_t off = (size_t)w * D + lane * 4;

    float4 a = *reinterpret_cast<const float4*>(g_acc + off);
    float4 x = *reinterpret_cast<const float4*>(vars + off);
    float4 vv = make_float4(x.x - a.x * inv, x.y - a.y * inv,
                            x.z - a.z * inv, x.w - a.w * inv);
    float ss = vv.x * vv.x + vv.y * vv.y + vv.z * vv.z + vv.w * vv.w;
    #pragma unroll
    for (int o = 16; o; o >>= 1) ss += __shfl_xor_sync(0xffffffffu, ss, o);
    float scale = rsqrtf(ss * (1.0f / 128.0f) + EPSILON);
    *reinterpret_cast<float4*>(out + off) =
        make_float4(vv.x * scale, vv.y * scale, vv.z * scale, vv.w * scale);
}

// ---------------- launcher ---------------------------------------------------
extern "C" void kernel_launch(void* const* d_in, const int* in_sizes, int n_in,
                              void* d_out, int out_size) {
    const float* vars = (const float*)d_in[0];
    const float* vals = (const float*)d_in[1];
    const int*   rows = (const int*)d_in[2];
    const int*   cols = (const int*)d_in[3];
    float* out = (float*)d_out;

    k_init <<<1024, 256>>>(vars);
    k_build<<<(NNZ + 255) / 256, 256>>>(rows, cols, vals);
    k_fused<<<(N_CLAUSES * 32 + 255) / 256, 256>>>();
    k_norm <<<(N_VARS * 32 + 255) / 256, 256>>>(vars, out);
}

// round 16
// speedup vs baseline: 4.0171x; 1.1247x over previous
#include <cuda_runtime.h>
#include <cuda_fp16.h>

#define N_VARS    100000
#define N_CLAUSES 400000
#define NNZ       1200000
#define D         128
#define EPSILON   1e-6f
#define CAP       32          // per-clause smem edge cache (avg degree ~3)

// ---------------- scratch (static device globals; ~72 MB => L2-resident) -----
struct __align__(16) EdgeRec { int next; int col; float val; int pad; };

__device__ uint2   g_varsh[(size_t)N_VARS * 32];  // vars fp16: [var][lane], 25.6 MB
__device__ uint2   g_acch[(size_t)N_VARS * 32];   // fp16 accumulator, 25.6 MB
__device__ float   g_vdeg[N_VARS];
__device__ int     g_head[N_CLAUSES];
__device__ EdgeRec g_rec[NNZ];                    // 19.2 MB

// vector fp16 reduction: adds 4 halves (two f16x2 words) in one instruction
__device__ __forceinline__ void red_add_h4(uint2* p, unsigned h0, unsigned h1) {
    asm volatile("red.global.add.noftz.v2.f16x2 [%0], {%1,%2};"
                 :: "l"(p), "r"(h0), "r"(h1) : "memory");
}
__device__ __forceinline__ void red_add_f(float* p, float v) {
    asm volatile("red.global.add.f32 [%0], %1;" :: "l"(p), "f"(v) : "memory");
}

// ---------------- init: zero acc/vdeg, head=-1, convert vars to fp16 ---------
__global__ void k_init(const float* __restrict__ vars) {
    int tid    = blockIdx.x * blockDim.x + threadIdx.x;
    int stride = gridDim.x * blockDim.x;
    const int nh = N_VARS * 32;                 // uint2 words (4 feats each)
    uint2 z2 = make_uint2(0u, 0u);
    for (int i = tid; i < nh; i += stride) g_acch[i] = z2;
    for (int i = tid; i < N_VARS;    i += stride) g_vdeg[i] = 0.f;
    for (int i = tid; i < N_CLAUSES; i += stride) g_head[i] = -1;

    const float4* v4 = reinterpret_cast<const float4*>(vars);
    for (int i = tid; i < nh; i += stride) {
        float4 x = v4[i];
        __half2 h0 = __floats2half2_rn(x.x, x.y);
        __half2 h1 = __floats2half2_rn(x.z, x.w);
        g_varsh[i] = make_uint2(*reinterpret_cast<unsigned*>(&h0),
                                *reinterpret_cast<unsigned*>(&h1));
    }
}

// ---------------- build per-clause linked lists ------------------------------
__global__ void k_build(const int* __restrict__ rows,
                        const int* __restrict__ cols,
                        const float* __restrict__ vals) {
    int e = blockIdx.x * blockDim.x + threadIdx.x;
    if (e >= NNZ) return;
    int r = __ldg(rows + e);
    int prev = atomicExch(&g_head[r], e);
    int col = __ldg(cols + e);
    float v = __ldg(vals + e);
    int vv = (col >= N_VARS) ? (col - N_VARS) : col;   // fold literal halves
    *reinterpret_cast<int4*>(&g_rec[e]) = make_int4(prev, vv, __float_as_int(v), 0);
}

// ---------------- fused A^T A pass: one warp per clause ----------------------
// Gather fp16 var rows into fp32 register sum, then RED-scatter fp16 messages
// back to each incident variable (one v2.f16x2 RED per edge per lane).
__global__ void __launch_bounds__(256)
k_fused() {
    int w = (blockIdx.x * blockDim.x + threadIdx.x) >> 5;
    if (w >= N_CLAUSES) return;
    int lane  = threadIdx.x & 31;
    int wslot = (threadIdx.x >> 5);
    __shared__ uint2 list[8][CAP];   // (v, val) per cached edge

    int e = g_head[w];
    if (e < 0) return;

    float4 sum = make_float4(0.f, 0.f, 0.f, 0.f);
    float  deg = 0.f;
    int cnt = 0;
    int e_rest = -1;

    while (e >= 0) {
        int4 r = *reinterpret_cast<const int4*>(&g_rec[e]);  // uniform addr, bcast
        int   v   = r.y;
        float val = __int_as_float(r.z);

        uint2 h = __ldg(&g_varsh[(size_t)v * 32 + lane]);    // 256 B/warp, fp16
        float2 f0 = __half22float2(*reinterpret_cast<__half2*>(&h.x));
        float2 f1 = __half22float2(*reinterpret_cast<__half2*>(&h.y));
        sum.x += f0.x * val;  sum.y += f0.y * val;
        sum.z += f1.x * val;  sum.w += f1.y * val;
        deg   += val;

        if (cnt < CAP) {
            if (lane == 0) list[wslot][cnt] = make_uint2((unsigned)v, (unsigned)r.z);
            cnt++;
        } else if (e_rest < 0) {
            e_rest = e;   // overflow tail (practically never)
        }
        e = r.x;
    }
    __syncwarp();

    for (int i = 0; i < cnt; i++) {
        uint2 u = list[wslot][i];
        int   v   = (int)u.x;
        float val = __uint_as_float(u.y);
        __half2 m0 = __floats2half2_rn(sum.x * val, sum.y * val);
        __half2 m1 = __floats2half2_rn(sum.z * val, sum.w * val);
        red_add_h4(&g_acch[(size_t)v * 32 + lane],
                   *reinterpret_cast<unsigned*>(&m0),
                   *reinterpret_cast<unsigned*>(&m1));
        if (lane == 0) red_add_f(&g_vdeg[v], deg * val);
    }

    while (e_rest >= 0) {   // overflow tail for clauses with >CAP edges
        int4 r = *reinterpret_cast<const int4*>(&g_rec[e_rest]);
        int   v   = r.y;
        float val = __int_as_float(r.z);
        __half2 m0 = __floats2half2_rn(sum.x * val, sum.y * val);
        __half2 m1 = __floats2half2_rn(sum.z * val, sum.w * val);
        red_add_h4(&g_acch[(size_t)v * 32 + lane],
                   *reinterpret_cast<unsigned*>(&m0),
                   *reinterpret_cast<unsigned*>(&m1));
        if (lane == 0) red_add_f(&g_vdeg[v], deg * val);
        e_rest = r.x;
    }
}

// ---------------- normalize: one warp per variable ---------------------------
__global__ void k_norm(const float* __restrict__ vars, float* __restrict__ out) {
    int w = (blockIdx.x * blockDim.x + threadIdx.x) >> 5;
    if (w >= N_VARS) return;
    int lane = threadIdx.x & 31;

    float deg = g_vdeg[w];
    float inv = 1.0f / fmaxf(deg, 2.0f);
    size_t off = (size_t)w * D + lane * 4;

    uint2 ah = g_acch[(size_t)w * 32 + lane];
    float2 a0 = __half22float2(*reinterpret_cast<__half2*>(&ah.x));
    float2 a1 = __half22float2(*reinterpret_cast<__half2*>(&ah.y));

    float4 x = *reinterpret_cast<const float4*>(vars + off);
    float4 vv = make_float4(x.x - a0.x * inv, x.y - a0.y * inv,
                            x.z - a1.x * inv, x.w - a1.y * inv);
    float ss = vv.x * vv.x + vv.y * vv.y + vv.z * vv.z + vv.w * vv.w;
    #pragma unroll
    for (int o = 16; o; o >>= 1) ss += __shfl_xor_sync(0xffffffffu, ss, o);
    float scale = rsqrtf(ss * (1.0f / 128.0f) + EPSILON);
    *reinterpret_cast<float4*>(out + off) =
        make_float4(vv.x * scale, vv.y * scale, vv.z * scale, vv.w * scale);
}

// ---------------- launcher ---------------------------------------------------
extern "C" void kernel_launch(void* const* d_in, const int* in_sizes, int n_in,
                              void* d_out, int out_size) {
    const float* vars = (const float*)d_in[0];
    const float* vals = (const float*)d_in[1];
    const int*   rows = (const int*)d_in[2];
    const int*   cols = (const int*)d_in[3];
    float* out = (float*)d_out;

    k_init <<<1024, 256>>>(vars);
    k_build<<<(NNZ + 255) / 256, 256>>>(rows, cols, vals);
    k_fused<<<(N_CLAUSES * 32 + 255) / 256, 256>>>();
    k_norm <<<(N_VARS * 32 + 255) / 256, 256>>>(vars, out);
}